// round 1
// baseline (speedup 1.0000x reference)
#include <cuda_runtime.h>
#include <cstdint>

#define BB 128    // batch
#define SS 64     // src seq len
#define HH 1280   // hidden
#define EE 256    // embedding
#define VV 32000  // vocab
#define GG 3840   // 3*H
#define KXX 1536  // H + E

// ---------------- scratch (device globals: allocation-free) ----------------
__device__ float g_whdot[BB];
__device__ float g_scores[SS * BB];
__device__ float g_x[BB * KXX];
__device__ float g_gi[BB * GG];
__device__ float g_gh[BB * GG];
__device__ float g_logits[(size_t)BB * VV];
__device__ float g_logZ[BB];
__device__ float g_hnew_scratch[BB * HH];
__device__ float g_aw_scratch[SS * BB];

// ---------------- helpers ----------------
__device__ __forceinline__ float warp_sum(float v) {
    #pragma unroll
    for (int off = 16; off; off >>= 1) v += __shfl_xor_sync(0xffffffffu, v, off);
    return v;
}

__device__ __forceinline__ uint32_t f2tf(float f) {
    uint32_t r;
    asm("cvt.rna.tf32.f32 %0, %1;" : "=r"(r) : "f"(f));
    return r;
}

__device__ __forceinline__ void mma8(float* d,
                                     uint32_t a0, uint32_t a1, uint32_t a2, uint32_t a3,
                                     uint32_t b0, uint32_t b1) {
    asm volatile(
        "mma.sync.aligned.m16n8k8.row.col.f32.tf32.tf32.f32 "
        "{%0,%1,%2,%3}, {%4,%5,%6,%7}, {%8,%9}, {%0,%1,%2,%3};"
        : "+f"(d[0]), "+f"(d[1]), "+f"(d[2]), "+f"(d[3])
        : "r"(a0), "r"(a1), "r"(a2), "r"(a3), "r"(b0), "r"(b1));
}

__device__ __forceinline__ float sigm(float x) { return 1.f / (1.f + expf(-x)); }

// ---------------- kernel 1a: attention score dot products ----------------
// warps [0, S*B):   g_scores[r] = enc_flat[r] . w_e
// warps [S*B, +B):  g_whdot[b]  = h0[b] . w_h
__global__ void __launch_bounds__(256) attn_scores_kernel(
    const float* __restrict__ enc, const float* __restrict__ h0,
    const float* __restrict__ attn_w)
{
    int warp = (blockIdx.x * blockDim.x + threadIdx.x) >> 5;
    int lane = threadIdx.x & 31;
    if (warp < SS * BB) {
        const float4* row = (const float4*)(enc + (size_t)warp * HH);
        const float4* w   = (const float4*)(attn_w + HH);  // w_e
        float acc = 0.f;
        #pragma unroll 5
        for (int i = lane; i < HH / 4; i += 32) {
            float4 a = row[i], b = w[i];
            acc += a.x * b.x + a.y * b.y + a.z * b.z + a.w * b.w;
        }
        acc = warp_sum(acc);
        if (lane == 0) g_scores[warp] = acc;
    } else if (warp < SS * BB + BB) {
        int b = warp - SS * BB;
        const float4* row = (const float4*)(h0 + (size_t)b * HH);
        const float4* w   = (const float4*)(attn_w);       // w_h
        float acc = 0.f;
        #pragma unroll 5
        for (int i = lane; i < HH / 4; i += 32) {
            float4 a = row[i], bb = w[i];
            acc += a.x * bb.x + a.y * bb.y + a.z * bb.z + a.w * bb.w;
        }
        acc = warp_sum(acc);
        if (lane == 0) g_whdot[b] = acc;
    }
}

// ---------------- kernel 1b: softmax over batch dim per s, writes aw ----------------
__global__ void attn_softmax_kernel(const float* __restrict__ attn_b,
                                    float* __restrict__ aw_out)
{
    int s = blockIdx.x, b = threadIdx.x;  // 128 threads
    float v = g_scores[s * BB + b] + g_whdot[b] + attn_b[0];
    __shared__ float red[BB];
    red[b] = v;
    __syncthreads();
    #pragma unroll
    for (int off = 64; off; off >>= 1) {
        if (b < off) red[b] = fmaxf(red[b], red[b + off]);
        __syncthreads();
    }
    float m = red[0];
    __syncthreads();
    float e = expf(v - m);
    red[b] = e;
    __syncthreads();
    #pragma unroll
    for (int off = 64; off; off >>= 1) {
        if (b < off) red[b] += red[b + off];
        __syncthreads();
    }
    aw_out[s * BB + b] = e / red[0];
}

// ---------------- kernel 1c: ctx (flat 64-row weighted sum) + emb gather + relu ----------------
// ctx[i,:] = sum_j aw_flat[i*64+j] * enc_flat[i*64+j, :]   (rows are contiguous!)
__global__ void __launch_bounds__(320) ctx_x_kernel(
    const float* __restrict__ enc, const float* __restrict__ embedding,
    const int* __restrict__ dec_in, const float* __restrict__ aw)
{
    int i = blockIdx.x, t = threadIdx.x;  // 320 threads = HH/4
    __shared__ float a[SS];
    if (t < SS) a[t] = aw[i * SS + t];
    __syncthreads();
    const float4* ef = (const float4*)enc;
    size_t base = (size_t)(i * SS) * (HH / 4) + t;
    float4 acc = make_float4(0.f, 0.f, 0.f, 0.f);
    #pragma unroll 8
    for (int j = 0; j < SS; j++) {
        float4 v = ef[base + (size_t)j * (HH / 4)];
        float w = a[j];
        acc.x += w * v.x; acc.y += w * v.y; acc.z += w * v.z; acc.w += w * v.w;
    }
    float4* xr = (float4*)(g_x + (size_t)i * KXX);
    xr[t] = make_float4(fmaxf(acc.x, 0.f), fmaxf(acc.y, 0.f),
                        fmaxf(acc.z, 0.f), fmaxf(acc.w, 0.f));
    if (t < EE / 4) {
        int row = dec_in[i];
        float4 e4 = ((const float4*)embedding)[(size_t)row * (EE / 4) + t];
        xr[HH / 4 + t] = make_float4(fmaxf(e4.x, 0.f), fmaxf(e4.y, 0.f),
                                     fmaxf(e4.z, 0.f), fmaxf(e4.w, 0.f));
    }
}

// ---------------- tf32 GEMM core: C[128, N] = A[128,K] @ W[N,K]^T + bias ----------------
// 256 threads, WM x WN warp grid, CTA tile 128 x NTILE, permuted-K float4 loads.
template <int NTILE, int WM, int WN, int K>
__device__ __forceinline__ void gemm_core(
    const float* __restrict__ A, const float* __restrict__ W,
    const float* __restrict__ bias, float* __restrict__ C, int ldc)
{
    constexpr int MT = (128 / WM) / 16;     // m16 tiles per warp
    constexpr int NT = (NTILE / WN) / 8;    // n8 tiles per warp
    int warp = threadIdx.x >> 5, lane = threadIdx.x & 31;
    int wm = warp % WM, wn = warp / WM;
    int mrow = wm * (128 / WM);
    int ncol = blockIdx.x * NTILE + wn * (NTILE / WN);
    int gid = lane >> 2, tig = lane & 3;

    float acc[MT][NT][4];
    #pragma unroll
    for (int mt = 0; mt < MT; mt++)
        #pragma unroll
        for (int nt = 0; nt < NT; nt++)
            #pragma unroll
            for (int q = 0; q < 4; q++) acc[mt][nt][q] = 0.f;

    for (int kk = 0; kk < K; kk += 16) {
        float4 av0[MT], av1[MT], bv[NT];
        #pragma unroll
        for (int mt = 0; mt < MT; mt++) {
            int r0 = mrow + mt * 16 + gid;
            av0[mt] = *(const float4*)(A + (size_t)r0 * K + kk + tig * 4);
            av1[mt] = *(const float4*)(A + (size_t)(r0 + 8) * K + kk + tig * 4);
        }
        #pragma unroll
        for (int nt = 0; nt < NT; nt++) {
            int n = ncol + nt * 8 + gid;
            bv[nt] = *(const float4*)(W + (size_t)n * K + kk + tig * 4);
        }
        uint32_t at[MT][8];
        #pragma unroll
        for (int mt = 0; mt < MT; mt++) {
            at[mt][0] = f2tf(av0[mt].x); at[mt][1] = f2tf(av1[mt].x);
            at[mt][2] = f2tf(av0[mt].y); at[mt][3] = f2tf(av1[mt].y);
            at[mt][4] = f2tf(av0[mt].z); at[mt][5] = f2tf(av1[mt].z);
            at[mt][6] = f2tf(av0[mt].w); at[mt][7] = f2tf(av1[mt].w);
        }
        uint32_t bt[NT][4];
        #pragma unroll
        for (int nt = 0; nt < NT; nt++) {
            bt[nt][0] = f2tf(bv[nt].x); bt[nt][1] = f2tf(bv[nt].y);
            bt[nt][2] = f2tf(bv[nt].z); bt[nt][3] = f2tf(bv[nt].w);
        }
        #pragma unroll
        for (int mt = 0; mt < MT; mt++)
            #pragma unroll
            for (int nt = 0; nt < NT; nt++) {
                mma8(acc[mt][nt], at[mt][0], at[mt][1], at[mt][2], at[mt][3],
                     bt[nt][0], bt[nt][1]);
                mma8(acc[mt][nt], at[mt][4], at[mt][5], at[mt][6], at[mt][7],
                     bt[nt][2], bt[nt][3]);
            }
    }
    // epilogue
    #pragma unroll
    for (int mt = 0; mt < MT; mt++) {
        int r0 = mrow + mt * 16 + gid;
        #pragma unroll
        for (int nt = 0; nt < NT; nt++) {
            int c0 = ncol + nt * 8 + tig * 2;
            float b0 = bias[c0], b1 = bias[c0 + 1];
            C[(size_t)r0 * ldc + c0]           = acc[mt][nt][0] + b0;
            C[(size_t)r0 * ldc + c0 + 1]       = acc[mt][nt][1] + b1;
            C[(size_t)(r0 + 8) * ldc + c0]     = acc[mt][nt][2] + b0;
            C[(size_t)(r0 + 8) * ldc + c0 + 1] = acc[mt][nt][3] + b1;
        }
    }
}

// GRU GEMMs fused in one grid: y==0 -> gi = x@w_ih^T+b_ih; y==1 -> gh = h0@w_hh^T+b_hh
__global__ void __launch_bounds__(256, 1) gru_gemm_kernel(
    const float* __restrict__ h0,
    const float* __restrict__ w_ih, const float* __restrict__ w_hh,
    const float* __restrict__ b_ih, const float* __restrict__ b_hh)
{
    if (blockIdx.y == 0)
        gemm_core<64, 4, 2, KXX>(g_x, w_ih, b_ih, g_gi, GG);
    else
        gemm_core<64, 4, 2, HH>(h0, w_hh, b_hh, g_gh, GG);
}

__global__ void __launch_bounds__(256, 1) dense_gemm_kernel(
    const float* __restrict__ hnew,
    const float* __restrict__ dw, const float* __restrict__ db)
{
    gemm_core<128, 2, 4, HH>(hnew, dw, db, g_logits, VV);
}

// ---------------- GRU gate elementwise ----------------
__global__ void gru_gates_kernel(const float* __restrict__ h0,
                                 float* __restrict__ hnew_out)
{
    int idx = blockIdx.x * blockDim.x + threadIdx.x;  // 128*1280
    int b = idx / HH, h = idx % HH;
    size_t o = (size_t)b * GG + h;
    float r = sigm(g_gi[o] + g_gh[o]);
    float z = sigm(g_gi[o + HH] + g_gh[o + HH]);
    float n = tanhf(g_gi[o + 2 * HH] + r * g_gh[o + 2 * HH]);
    float h0v = h0[idx];
    hnew_out[idx] = (1.f - z) * n + z * h0v;
}

// ---------------- per-row online logsumexp over 32000 logits ----------------
__global__ void lse_kernel() {
    int row = blockIdx.x, t = threadIdx.x;  // 256 threads
    const float4* p = (const float4*)(g_logits + (size_t)row * VV);
    float m = -3.402823466e38f, s = 0.f;
    for (int i = t; i < VV / 4; i += 256) {
        float4 v = p[i];
        float mv = fmaxf(fmaxf(v.x, v.y), fmaxf(v.z, v.w));
        float mn = fmaxf(m, mv);
        s = s * expf(m - mn) + expf(v.x - mn) + expf(v.y - mn)
          + expf(v.z - mn) + expf(v.w - mn);
        m = mn;
    }
    __shared__ float sm[256], ss[256];
    sm[t] = m; ss[t] = s;
    __syncthreads();
    #pragma unroll
    for (int off = 128; off; off >>= 1) {
        if (t < off) {
            float m2 = sm[t + off], s2 = ss[t + off];
            float mn = fmaxf(sm[t], m2);
            ss[t] = ss[t] * expf(sm[t] - mn) + s2 * expf(m2 - mn);
            sm[t] = mn;
        }
        __syncthreads();
    }
    if (t == 0) g_logZ[row] = sm[0] + logf(ss[0]);
}

// ---------------- logp writeback ----------------
__global__ void logp_kernel(float* __restrict__ out) {
    int idx = blockIdx.x * blockDim.x + threadIdx.x;
    const int total = BB * (VV / 4);
    for (int i = idx; i < total; i += gridDim.x * blockDim.x) {
        int row = i / (VV / 4);
        float4 v = ((const float4*)g_logits)[i];
        float z = g_logZ[row];
        v.x -= z; v.y -= z; v.z -= z; v.w -= z;
        ((float4*)out)[i] = v;
    }
}

// ---------------- launch ----------------
extern "C" void kernel_launch(void* const* d_in, const int* in_sizes, int n_in,
                              void* d_out, int out_size) {
    const int*   dec    = (const int*)d_in[0];
    const float* h0     = (const float*)d_in[1];
    const float* enc    = (const float*)d_in[2];
    const float* emb    = (const float*)d_in[3];
    const float* attn_w = (const float*)d_in[4];
    const float* attn_b = (const float*)d_in[5];
    const float* w_ih   = (const float*)d_in[6];
    const float* w_hh   = (const float*)d_in[7];
    const float* b_ih   = (const float*)d_in[8];
    const float* b_hh   = (const float*)d_in[9];
    const float* dw     = (const float*)d_in[10];
    const float* db     = (const float*)d_in[11];

    float* out  = (float*)d_out;
    const size_t full = (size_t)BB * VV + (size_t)BB * HH + (size_t)SS * BB;
    float* logp = out;
    float* hnew;
    float* aw;
    if ((size_t)out_size >= full) {
        hnew = out + (size_t)BB * VV;
        aw   = hnew + (size_t)BB * HH;
    } else {
        // fallback: harness only wants logp; keep the rest in scratch
        float* dummy_h; cudaGetSymbolAddress((void**)&dummy_h, g_hnew_scratch);
        float* dummy_a; cudaGetSymbolAddress((void**)&dummy_a, g_aw_scratch);
        hnew = dummy_h;
        aw   = dummy_a;
    }

    attn_scores_kernel<<<(SS * BB + BB) / 8, 256>>>(enc, h0, attn_w);
    attn_softmax_kernel<<<SS, BB>>>(attn_b, aw);
    ctx_x_kernel<<<BB, 320>>>(enc, emb, dec, aw);
    gru_gemm_kernel<<<dim3(GG / 64, 2), 256>>>(h0, w_ih, w_hh, b_ih, b_hh);
    gru_gates_kernel<<<BB * HH / 256, 256>>>(h0, hnew);
    dense_gemm_kernel<<<VV / 128, 256>>>(hnew, dw, db);
    lse_kernel<<<BB, 256>>>();
    logp_kernel<<<2048, 256>>>(logp);
}

// round 2
// speedup vs baseline: 1.2330x; 1.2330x over previous
#include <cuda_runtime.h>
#include <cstdint>

#define BB 128    // batch
#define SS 64     // src seq len
#define HH 1280   // hidden
#define EE 256    // embedding
#define VV 32000  // vocab
#define GG 3840   // 3*H
#define KXX 1536  // H + E

#define KC  32    // k-chunk per pipeline stage
#define KCP 36    // padded smem stride (floats)

#define NCTA_D 250          // dense CTAs (VV/128)
#define PSTRIDE 256         // partial-lse stride

// ---------------- scratch (device globals: allocation-free) ----------------
__device__ float g_whdot[BB];
__device__ float g_scores[SS * BB];
__device__ float g_x[BB * KXX];
__device__ float g_gi[BB * GG];
__device__ float g_gh[BB * GG];
__device__ float g_logits[(size_t)BB * VV];
__device__ float g_logZ[BB];
__device__ float g_pm[BB * PSTRIDE];
__device__ float g_ps[BB * PSTRIDE];
__device__ float g_hnew_scratch[BB * HH];
__device__ float g_aw_scratch[SS * BB];

// ---------------- helpers ----------------
__device__ __forceinline__ float warp_sum(float v) {
    #pragma unroll
    for (int off = 16; off; off >>= 1) v += __shfl_xor_sync(0xffffffffu, v, off);
    return v;
}

__device__ __forceinline__ void cp16(uint32_t s, const void* g) {
    asm volatile("cp.async.cg.shared.global [%0], [%1], 16;" :: "r"(s), "l"(g));
}

__device__ __forceinline__ void mma8(float* d,
                                     uint32_t a0, uint32_t a1, uint32_t a2, uint32_t a3,
                                     uint32_t b0, uint32_t b1) {
    asm volatile(
        "mma.sync.aligned.m16n8k8.row.col.f32.tf32.tf32.f32 "
        "{%0,%1,%2,%3}, {%4,%5,%6,%7}, {%8,%9}, {%0,%1,%2,%3};"
        : "+f"(d[0]), "+f"(d[1]), "+f"(d[2]), "+f"(d[3])
        : "r"(a0), "r"(a1), "r"(a2), "r"(a3), "r"(b0), "r"(b1));
}

__device__ __forceinline__ float sigm(float x) { return 1.f / (1.f + expf(-x)); }

// ---------------- pipelined tf32 GEMM core ----------------
// C[128, NTILE-slice] = A[128,K] @ W[N,K]^T (+ bias).  Raw fp32 bits fed to
// tf32 MMA (HW truncates mantissa).  cp.async S-stage double buffering.
template <int NTILE, int K, int S, int WM, int WN, bool FUSE>
__device__ __forceinline__ void gemm_pipe(
    float* __restrict__ sh,
    const float* __restrict__ A, const float* __restrict__ W,
    const float* __restrict__ bias, float* __restrict__ C, int ldc,
    int ncol, int cta)
{
    constexpr int A_FLOATS = 128 * KCP;
    constexpr int B_FLOATS = NTILE * KCP;
    constexpr int STAGE = A_FLOATS + B_FLOATS;
    constexpr int NITER = K / KC;
    constexpr int MT = (128 / WM) / 16;
    constexpr int NT = (NTILE / WN) / 8;

    const int tid  = threadIdx.x;
    const int warp = tid >> 5, lane = tid & 31;
    const int wm = warp % WM, wn = warp / WM;
    const int gid = lane >> 2, tig = lane & 3;
    const int mbase = wm * (128 / WM);
    const int nbase = wn * (NTILE / WN);

    const int lrow = tid >> 3;          // 0..31
    const int lc4  = (tid & 7) * 4;     // float col offset

    auto load_stage = [&](int slot, int kk) {
        float* sA = sh + slot * STAGE;
        float* sB = sA + A_FLOATS;
        #pragma unroll
        for (int r = 0; r < 4; r++) {
            int rr = lrow + r * 32;
            cp16((uint32_t)__cvta_generic_to_shared(sA + rr * KCP + lc4),
                 A + (size_t)rr * K + kk + lc4);
        }
        #pragma unroll
        for (int r = 0; r < NTILE / 32; r++) {
            int rr = lrow + r * 32;
            cp16((uint32_t)__cvta_generic_to_shared(sB + rr * KCP + lc4),
                 W + (size_t)(ncol + rr) * K + kk + lc4);
        }
        asm volatile("cp.async.commit_group;");
    };

    #pragma unroll
    for (int st = 0; st < S - 1; st++) load_stage(st, st * KC);

    float acc[MT][NT][4];
    #pragma unroll
    for (int mt = 0; mt < MT; mt++)
        #pragma unroll
        for (int nt = 0; nt < NT; nt++)
            #pragma unroll
            for (int q = 0; q < 4; q++) acc[mt][nt][q] = 0.f;

    for (int it = 0; it < NITER; it++) {
        asm volatile("cp.async.wait_group %0;" :: "n"(S - 2));
        __syncthreads();
        if (it + S - 1 < NITER) load_stage((it + S - 1) % S, (it + S - 1) * KC);

        const float* sA = sh + (it % S) * STAGE;
        const float* sB = sA + A_FLOATS;
        #pragma unroll
        for (int sub = 0; sub < KC / 16; sub++) {
            const int kb = sub * 16 + tig * 4;
            uint32_t at[MT][8];
            #pragma unroll
            for (int mt = 0; mt < MT; mt++) {
                int r0 = mbase + mt * 16 + gid;
                float4 a0 = *(const float4*)(sA + r0 * KCP + kb);
                float4 a1 = *(const float4*)(sA + (r0 + 8) * KCP + kb);
                at[mt][0] = __float_as_uint(a0.x); at[mt][1] = __float_as_uint(a1.x);
                at[mt][2] = __float_as_uint(a0.y); at[mt][3] = __float_as_uint(a1.y);
                at[mt][4] = __float_as_uint(a0.z); at[mt][5] = __float_as_uint(a1.z);
                at[mt][6] = __float_as_uint(a0.w); at[mt][7] = __float_as_uint(a1.w);
            }
            uint32_t bt[NT][4];
            #pragma unroll
            for (int nt = 0; nt < NT; nt++) {
                int n = nbase + nt * 8 + gid;
                float4 b = *(const float4*)(sB + n * KCP + kb);
                bt[nt][0] = __float_as_uint(b.x); bt[nt][1] = __float_as_uint(b.y);
                bt[nt][2] = __float_as_uint(b.z); bt[nt][3] = __float_as_uint(b.w);
            }
            #pragma unroll
            for (int mt = 0; mt < MT; mt++)
                #pragma unroll
                for (int nt = 0; nt < NT; nt++) {
                    mma8(acc[mt][nt], at[mt][0], at[mt][1], at[mt][2], at[mt][3],
                         bt[nt][0], bt[nt][1]);
                    mma8(acc[mt][nt], at[mt][4], at[mt][5], at[mt][6], at[mt][7],
                         bt[nt][2], bt[nt][3]);
                }
        }
    }

    // ---------------- epilogue ----------------
    if (!FUSE) {
        #pragma unroll
        for (int mt = 0; mt < MT; mt++) {
            #pragma unroll
            for (int h = 0; h < 2; h++) {
                int r = mbase + mt * 16 + gid + h * 8;
                #pragma unroll
                for (int nt = 0; nt < NT; nt++) {
                    int c = ncol + nbase + nt * 8 + tig * 2;
                    C[(size_t)r * ldc + c]     = acc[mt][nt][h * 2]     + bias[c];
                    C[(size_t)r * ldc + c + 1] = acc[mt][nt][h * 2 + 1] + bias[c + 1];
                }
            }
        }
    } else {
        __syncthreads();  // smem reuse for reductions
        float* rm = sh;            // [WN][128]
        float* rs = sh + WN * 128; // [WN][128]
        #pragma unroll
        for (int mt = 0; mt < MT; mt++) {
            #pragma unroll
            for (int h = 0; h < 2; h++) {
                int rl = mbase + mt * 16 + gid + h * 8;
                float m = -1e30f, s = 0.f;
                #pragma unroll
                for (int nt = 0; nt < NT; nt++) {
                    int c = ncol + nbase + nt * 8 + tig * 2;
                    float v0 = acc[mt][nt][h * 2]     + bias[c];
                    float v1 = acc[mt][nt][h * 2 + 1] + bias[c + 1];
                    C[(size_t)rl * ldc + c]     = v0;
                    C[(size_t)rl * ldc + c + 1] = v1;
                    float nm = fmaxf(m, fmaxf(v0, v1));
                    s = s * expf(m - nm) + expf(v0 - nm) + expf(v1 - nm);
                    m = nm;
                }
                // reduce over tig (lanes gid*4 + tig)
                #pragma unroll
                for (int o = 1; o < 4; o <<= 1) {
                    float m2 = __shfl_xor_sync(0xffffffffu, m, o);
                    float s2 = __shfl_xor_sync(0xffffffffu, s, o);
                    float nm = fmaxf(m, m2);
                    s = s * expf(m - nm) + s2 * expf(m2 - nm);
                    m = nm;
                }
                if (tig == 0) { rm[wn * 128 + rl] = m; rs[wn * 128 + rl] = s; }
            }
        }
        __syncthreads();
        if (tid < 128) {
            float m = rm[tid], s = rs[tid];
            #pragma unroll
            for (int w = 1; w < WN; w++) {
                float m2 = rm[w * 128 + tid], s2 = rs[w * 128 + tid];
                float nm = fmaxf(m, m2);
                s = s * expf(m - nm) + s2 * expf(m2 - nm);
                m = nm;
            }
            g_pm[tid * PSTRIDE + cta] = m;
            g_ps[tid * PSTRIDE + cta] = s;
        }
    }
}

// ---------------- kernel 1a: attention score dot products ----------------
__global__ void __launch_bounds__(256) attn_scores_kernel(
    const float* __restrict__ enc, const float* __restrict__ h0,
    const float* __restrict__ attn_w)
{
    int warp = (blockIdx.x * blockDim.x + threadIdx.x) >> 5;
    int lane = threadIdx.x & 31;
    if (warp < SS * BB) {
        const float4* row = (const float4*)(enc + (size_t)warp * HH);
        const float4* w   = (const float4*)(attn_w + HH);  // w_e
        float acc = 0.f;
        #pragma unroll 10
        for (int i = lane; i < HH / 4; i += 32) {
            float4 a = row[i], b = w[i];
            acc += a.x * b.x + a.y * b.y + a.z * b.z + a.w * b.w;
        }
        acc = warp_sum(acc);
        if (lane == 0) g_scores[warp] = acc;
    } else if (warp < SS * BB + BB) {
        int b = warp - SS * BB;
        const float4* row = (const float4*)(h0 + (size_t)b * HH);
        const float4* w   = (const float4*)(attn_w);       // w_h
        float acc = 0.f;
        #pragma unroll 10
        for (int i = lane; i < HH / 4; i += 32) {
            float4 a = row[i], bb = w[i];
            acc += a.x * bb.x + a.y * bb.y + a.z * bb.z + a.w * bb.w;
        }
        acc = warp_sum(acc);
        if (lane == 0) g_whdot[b] = acc;
    }
}

// ---------------- kernel 1b: softmax over batch dim per s ----------------
__global__ void attn_softmax_kernel(const float* __restrict__ attn_b,
                                    float* __restrict__ aw_out)
{
    int s = blockIdx.x, b = threadIdx.x;  // 128 threads
    float v = g_scores[s * BB + b] + g_whdot[b] + attn_b[0];
    __shared__ float red[BB];
    red[b] = v;
    __syncthreads();
    #pragma unroll
    for (int off = 64; off; off >>= 1) {
        if (b < off) red[b] = fmaxf(red[b], red[b + off]);
        __syncthreads();
    }
    float m = red[0];
    __syncthreads();
    float e = expf(v - m);
    red[b] = e;
    __syncthreads();
    #pragma unroll
    for (int off = 64; off; off >>= 1) {
        if (b < off) red[b] += red[b + off];
        __syncthreads();
    }
    aw_out[s * BB + b] = e / red[0];
}

// ---------------- kernel 1c: ctx + emb gather + relu ----------------
__global__ void __launch_bounds__(320) ctx_x_kernel(
    const float* __restrict__ enc, const float* __restrict__ embedding,
    const int* __restrict__ dec_in, const float* __restrict__ aw)
{
    int i = blockIdx.x, t = threadIdx.x;  // 320 threads = HH/4
    __shared__ float a[SS];
    if (t < SS) a[t] = aw[i * SS + t];
    __syncthreads();
    const float4* ef = (const float4*)enc;
    size_t base = (size_t)(i * SS) * (HH / 4) + t;
    float4 acc = make_float4(0.f, 0.f, 0.f, 0.f);
    #pragma unroll 16
    for (int j = 0; j < SS; j++) {
        float4 v = ef[base + (size_t)j * (HH / 4)];
        float w = a[j];
        acc.x += w * v.x; acc.y += w * v.y; acc.z += w * v.z; acc.w += w * v.w;
    }
    float4* xr = (float4*)(g_x + (size_t)i * KXX);
    xr[t] = make_float4(fmaxf(acc.x, 0.f), fmaxf(acc.y, 0.f),
                        fmaxf(acc.z, 0.f), fmaxf(acc.w, 0.f));
    if (t < EE / 4) {
        int row = dec_in[i];
        float4 e4 = ((const float4*)embedding)[(size_t)row * (EE / 4) + t];
        xr[HH / 4 + t] = make_float4(fmaxf(e4.x, 0.f), fmaxf(e4.y, 0.f),
                                     fmaxf(e4.z, 0.f), fmaxf(e4.w, 0.f));
    }
}

// ---------------- GEMM kernels ----------------
#define GRU_STAGE_FLOATS ((128 + 64) * KCP)
#define GRU_SMEM (4 * GRU_STAGE_FLOATS * 4)        // 110592 B
#define DENSE_STAGE_FLOATS ((128 + 128) * KCP)
#define DENSE_SMEM (4 * DENSE_STAGE_FLOATS * 4)    // 147456 B

__global__ void __launch_bounds__(256) gru_gemm_kernel(
    const float* __restrict__ h0,
    const float* __restrict__ w_ih, const float* __restrict__ w_hh,
    const float* __restrict__ b_ih, const float* __restrict__ b_hh)
{
    extern __shared__ float sh[];
    int ncol = blockIdx.x * 64;
    if (blockIdx.y == 0)
        gemm_pipe<64, KXX, 4, 2, 4, false>(sh, g_x, w_ih, b_ih, g_gi, GG, ncol, 0);
    else
        gemm_pipe<64, HH, 4, 2, 4, false>(sh, h0, w_hh, b_hh, g_gh, GG, ncol, 0);
}

__global__ void __launch_bounds__(256) dense_gemm_kernel(
    const float* __restrict__ hnew,
    const float* __restrict__ dw, const float* __restrict__ db)
{
    extern __shared__ float sh[];
    gemm_pipe<128, HH, 4, 2, 4, true>(sh, hnew, dw, db, g_logits, VV,
                                      blockIdx.x * 128, blockIdx.x);
}

// ---------------- GRU gate elementwise ----------------
__global__ void gru_gates_kernel(const float* __restrict__ h0,
                                 float* __restrict__ hnew_out)
{
    int idx = blockIdx.x * blockDim.x + threadIdx.x;  // 128*1280
    int b = idx / HH, h = idx % HH;
    size_t o = (size_t)b * GG + h;
    float r = sigm(g_gi[o] + g_gh[o]);
    float z = sigm(g_gi[o + HH] + g_gh[o + HH]);
    float n = tanhf(g_gi[o + 2 * HH] + r * g_gh[o + 2 * HH]);
    float h0v = h0[idx];
    hnew_out[idx] = (1.f - z) * n + z * h0v;
}

// ---------------- combine per-CTA (m,s) partials -> logZ ----------------
__global__ void lse_combine_kernel() {
    int row = blockIdx.x, t = threadIdx.x;  // 256 threads
    float m = -1e30f, s = 0.f;
    if (t < NCTA_D) { m = g_pm[row * PSTRIDE + t]; s = g_ps[row * PSTRIDE + t]; }
    __shared__ float sm[256], ss[256];
    sm[t] = m; ss[t] = s;
    __syncthreads();
    #pragma unroll
    for (int off = 128; off; off >>= 1) {
        if (t < off) {
            float m2 = sm[t + off], s2 = ss[t + off];
            float nm = fmaxf(sm[t], m2);
            ss[t] = ss[t] * expf(sm[t] - nm) + s2 * expf(m2 - nm);
            sm[t] = nm;
        }
        __syncthreads();
    }
    if (t == 0) g_logZ[row] = sm[0] + logf(ss[0]);
}

// ---------------- logp writeback ----------------
__global__ void logp_kernel(float* __restrict__ out) {
    int idx = blockIdx.x * blockDim.x + threadIdx.x;
    const int total = BB * (VV / 4);
    for (int i = idx; i < total; i += gridDim.x * blockDim.x) {
        int row = i / (VV / 4);
        float4 v = ((const float4*)g_logits)[i];
        float z = g_logZ[row];
        v.x -= z; v.y -= z; v.z -= z; v.w -= z;
        ((float4*)out)[i] = v;
    }
}

// ---------------- launch ----------------
extern "C" void kernel_launch(void* const* d_in, const int* in_sizes, int n_in,
                              void* d_out, int out_size) {
    const int*   dec    = (const int*)d_in[0];
    const float* h0     = (const float*)d_in[1];
    const float* enc    = (const float*)d_in[2];
    const float* emb    = (const float*)d_in[3];
    const float* attn_w = (const float*)d_in[4];
    const float* attn_b = (const float*)d_in[5];
    const float* w_ih   = (const float*)d_in[6];
    const float* w_hh   = (const float*)d_in[7];
    const float* b_ih   = (const float*)d_in[8];
    const float* b_hh   = (const float*)d_in[9];
    const float* dw     = (const float*)d_in[10];
    const float* db     = (const float*)d_in[11];

    float* out  = (float*)d_out;
    const size_t full = (size_t)BB * VV + (size_t)BB * HH + (size_t)SS * BB;
    float* logp = out;
    float* hnew;
    float* aw;
    if ((size_t)out_size >= full) {
        hnew = out + (size_t)BB * VV;
        aw   = hnew + (size_t)BB * HH;
    } else {
        float* dummy_h; cudaGetSymbolAddress((void**)&dummy_h, g_hnew_scratch);
        float* dummy_a; cudaGetSymbolAddress((void**)&dummy_a, g_aw_scratch);
        hnew = dummy_h;
        aw   = dummy_a;
    }

    cudaFuncSetAttribute(gru_gemm_kernel,
                         cudaFuncAttributeMaxDynamicSharedMemorySize, GRU_SMEM);
    cudaFuncSetAttribute(dense_gemm_kernel,
                         cudaFuncAttributeMaxDynamicSharedMemorySize, DENSE_SMEM);

    attn_scores_kernel<<<(SS * BB + BB) / 8, 256>>>(enc, h0, attn_w);
    attn_softmax_kernel<<<SS, BB>>>(attn_b, aw);
    ctx_x_kernel<<<BB, 320>>>(enc, emb, dec, aw);
    gru_gemm_kernel<<<dim3(GG / 64, 2), 256, GRU_SMEM>>>(h0, w_ih, w_hh, b_ih, b_hh);
    gru_gates_kernel<<<BB * HH / 256, 256>>>(h0, hnew);
    dense_gemm_kernel<<<NCTA_D, 256, DENSE_SMEM>>>(hnew, dw, db);
    lse_combine_kernel<<<BB, 256>>>();
    logp_kernel<<<2048, 256>>>(logp);
}